// round 3
// baseline (speedup 1.0000x reference)
#include <cuda_runtime.h>
#include <cuda_bf16.h>
#include <math.h>

// Problem constants
#define TT 512
#define BB 64
#define II 300
#define HH 1000
#define G4 4000   // 4*H
#define NBLK 125  // persistent blocks (1 per SM, 125 <= 148)

// ---------------------------------------------------------------------------
// Device scratch (allocation-free: __device__ globals, loader-backed)
// ---------------------------------------------------------------------------
__device__ float g_xg[(size_t)TT * BB * G4];  // precomputed input gates [T,B,4H]
__device__ unsigned g_bar;                    // step barrier counter

// ---------------------------------------------------------------------------
// tf32 helpers
// ---------------------------------------------------------------------------
__device__ __forceinline__ unsigned f2tf32(float x) {
    unsigned y;
    asm("cvt.rna.tf32.f32 %0, %1;" : "=r"(y) : "f"(x));
    return y;
}

__device__ __forceinline__ void mma_tf32(float c[4], const unsigned a[4],
                                         unsigned b0, unsigned b1) {
    asm volatile(
        "mma.sync.aligned.m16n8k8.row.col.f32.tf32.tf32.f32 "
        "{%0,%1,%2,%3}, {%4,%5,%6,%7}, {%8,%9}, {%0,%1,%2,%3};"
        : "+f"(c[0]), "+f"(c[1]), "+f"(c[2]), "+f"(c[3])
        : "r"(a[0]), "r"(a[1]), "r"(a[2]), "r"(a[3]), "r"(b0), "r"(b1));
}

__device__ __forceinline__ float sigmoidf_(float x) {
    return 1.0f / (1.0f + expf(-x));
}

// ---------------------------------------------------------------------------
// Kernel 0: reset step barrier (per launch/replay)
// ---------------------------------------------------------------------------
__global__ void init_kernel() {
    if (threadIdx.x == 0 && blockIdx.x == 0) g_bar = 0u;
}

// ---------------------------------------------------------------------------
// Kernel 1: x_gates = inputs @ W_ih^T + (b_ih + b_hh)   (unchanged, works)
// ---------------------------------------------------------------------------
__global__ void __launch_bounds__(256) xgates_kernel(
    const float* __restrict__ X, const float* __restrict__ Wih,
    const float* __restrict__ b_ih, const float* __restrict__ b_hh)
{
    const int m0 = blockIdx.y * 64;
    const int n0 = blockIdx.x * 64;
    const int tid  = threadIdx.x;
    const int lane = tid & 31;
    const int warp = tid >> 5;
    const int wm = warp & 3;
    const int wn = warp >> 2;

    __shared__ unsigned a_s[64][17];
    __shared__ unsigned b_s[64][17];

    float acc[4][4];
#pragma unroll
    for (int s = 0; s < 4; ++s)
#pragma unroll
        for (int i = 0; i < 4; ++i) acc[s][i] = 0.0f;

    const int g_id = lane >> 2;
    const int t_id = lane & 3;

    for (int ch = 0; ch < 19; ++ch) {
        const int k0 = ch * 16;
#pragma unroll
        for (int it = 0; it < 4; ++it) {
            int i = tid + it * 256;
            int m = i >> 4, k = i & 15;
            float va = (k0 + k < II) ? X[(size_t)(m0 + m) * II + k0 + k] : 0.0f;
            a_s[m][k] = f2tf32(va);
            int r = n0 + m;
            float vb = (r < G4 && k0 + k < II) ? Wih[(size_t)r * II + k0 + k] : 0.0f;
            b_s[m][k] = f2tf32(vb);
        }
        __syncthreads();

#pragma unroll
        for (int kk = 0; kk < 2; ++kk) {
            const int kb = kk * 8;
            unsigned a[4];
            a[0] = a_s[wm * 16 + g_id][kb + t_id];
            a[1] = a_s[wm * 16 + g_id + 8][kb + t_id];
            a[2] = a_s[wm * 16 + g_id][kb + t_id + 4];
            a[3] = a_s[wm * 16 + g_id + 8][kb + t_id + 4];
#pragma unroll
            for (int s = 0; s < 4; ++s) {
                unsigned b0 = b_s[wn * 32 + s * 8 + g_id][kb + t_id];
                unsigned b1 = b_s[wn * 32 + s * 8 + g_id][kb + t_id + 4];
                mma_tf32(acc[s], a, b0, b1);
            }
        }
        __syncthreads();
    }

#pragma unroll
    for (int s = 0; s < 4; ++s) {
        int n = n0 + wn * 32 + s * 8 + 2 * t_id;
        int row = m0 + wm * 16 + g_id;
        if (n < G4) {
            float bia0 = b_ih[n] + b_hh[n];
            float bia1 = b_ih[n + 1] + b_hh[n + 1];
            g_xg[(size_t)row * G4 + n]           = acc[s][0] + bia0;
            g_xg[(size_t)row * G4 + n + 1]       = acc[s][1] + bia1;
            g_xg[(size_t)(row + 8) * G4 + n]     = acc[s][2] + bia0;
            g_xg[(size_t)(row + 8) * G4 + n + 1] = acc[s][3] + bia1;
        }
    }
}

// ---------------------------------------------------------------------------
// Kernel 2: persistent LSTM — all 512 steps in one launch.
//   125 blocks, each owns 8 h-columns (32 gate-rows of W_hh, resident in smem).
//   Per step: tf32 MMA gates = h_prev @ Whh_slice^T, fused cell update,
//   h_t written to out[t], global spin barrier between steps.
//   c lives in registers; x_gates prefetched into registers across the barrier.
// ---------------------------------------------------------------------------
// smem layout (words):
//   W_s  : 32 * 1004                  (stride 1004: 1004%32==12 -> conflict-free)
//   h_s  : 2 * 64 * 44                (stride 44:   44%32==12  -> conflict-free)
//   g_sm : 64 * 33 floats
#define WS_STRIDE 1004
#define HS_STRIDE 44
#define SMEM_WORDS (32 * WS_STRIDE + 2 * 64 * HS_STRIDE + 64 * 33)

__global__ void __launch_bounds__(256) lstm_persistent(
    const float* __restrict__ h0, const float* __restrict__ c0,
    const float* __restrict__ Whh, float* __restrict__ out)
{
    extern __shared__ unsigned sm[];
    unsigned* W_s = sm;                              // [32][1004]
    unsigned* h_s = sm + 32 * WS_STRIDE;             // [2][64][44]
    float*    g_sm = (float*)(sm + 32 * WS_STRIDE + 2 * 64 * HS_STRIDE); // [64][33]

    const int j0   = blockIdx.x * 8;
    const int tid  = threadIdx.x;
    const int lane = tid & 31;
    const int warp = tid >> 5;
    const int wm = warp & 3;       // m(batch)-warp: rows wm*16..+15
    const int wn = warp >> 2;      // n-warp: cols wn*16..+15
    const int g_id = lane >> 2;
    const int t_id = lane & 3;

    // ---- load W_hh slice into smem once (tf32), gate-major columns ----
    for (int idx = tid; idx < 32 * 1000; idx += 256) {
        int r = idx / 1000, k = idx - r * 1000;
        int gate = r >> 3;
        int row  = gate * HH + j0 + (r & 7);
        W_s[r * WS_STRIDE + k] = f2tf32(Whh[(size_t)row * HH + k]);
    }

    // ---- cell state in registers ----
    float c_reg[2];
#pragma unroll
    for (int q = 0; q < 2; ++q) {
        int e = tid + q * 256;
        int b = e >> 3, jj = e & 7;
        c_reg[q] = c0[b * HH + j0 + jj];
    }

    // ---- prefetch x_gates for t=0 ----
    float xg[2][4];
#pragma unroll
    for (int q = 0; q < 2; ++q) {
        int e = tid + q * 256;
        int b = e >> 3, jj = e & 7;
        const float* p = g_xg + (size_t)b * G4 + j0 + jj;
#pragma unroll
        for (int g = 0; g < 4; ++g) xg[q][g] = p[g * HH];
    }

    __syncthreads();

    // h staging assignment: thread -> (row hb, 10 consecutive k at hk)
    const int hb = tid >> 2;
    const int hk = (tid & 3) * 10;

    for (int t = 0; t < TT; ++t) {
        // ---- wait for h_{t-1} from all blocks ----
        if (t > 0) {
            if (tid == 0) {
                unsigned target = (unsigned)(NBLK * t);
                while (*(volatile unsigned*)&g_bar < target) { }
            }
            __syncthreads();
            __threadfence();
        }
        const float* hp = (t == 0) ? h0 : out + (size_t)(t - 1) * BB * HH;

        float acc[2][4];
#pragma unroll
        for (int s = 0; s < 2; ++s)
#pragma unroll
            for (int i = 0; i < 4; ++i) acc[s][i] = 0.0f;

        // ---- prologue: stage chunk 0 ----
        float r0[10];
#pragma unroll
        for (int j = 0; j < 10; ++j) r0[j] = hp[(size_t)hb * HH + hk + j];
#pragma unroll
        for (int j = 0; j < 10; ++j) h_s[hb * HS_STRIDE + hk + j] = f2tf32(r0[j]);
        __syncthreads();

        // ---- K loop: 25 chunks of 40, double-buffered ----
        for (int ch = 0; ch < 25; ++ch) {
            const int k0  = ch * 40;
            const int cur = (ch & 1) * 64 * HS_STRIDE;

            if (ch < 24) {
#pragma unroll
                for (int j = 0; j < 10; ++j)
                    r0[j] = hp[(size_t)hb * HH + k0 + 40 + hk + j];
            }

#pragma unroll
            for (int kk = 0; kk < 5; ++kk) {
                const int kb = kk * 8;
                unsigned a[4];
                a[0] = h_s[cur + (wm * 16 + g_id) * HS_STRIDE + kb + t_id];
                a[1] = h_s[cur + (wm * 16 + g_id + 8) * HS_STRIDE + kb + t_id];
                a[2] = h_s[cur + (wm * 16 + g_id) * HS_STRIDE + kb + t_id + 4];
                a[3] = h_s[cur + (wm * 16 + g_id + 8) * HS_STRIDE + kb + t_id + 4];
#pragma unroll
                for (int s = 0; s < 2; ++s) {
                    unsigned b0 = W_s[(wn * 16 + s * 8 + g_id) * WS_STRIDE + k0 + kb + t_id];
                    unsigned b1 = W_s[(wn * 16 + s * 8 + g_id) * WS_STRIDE + k0 + kb + t_id + 4];
                    mma_tf32(acc[s], a, b0, b1);
                }
            }
            __syncthreads();
            if (ch < 24) {
                const int nxt = ((ch + 1) & 1) * 64 * HS_STRIDE;
#pragma unroll
                for (int j = 0; j < 10; ++j)
                    h_s[nxt + hb * HS_STRIDE + hk + j] = f2tf32(r0[j]);
                __syncthreads();
            }
        }

        // ---- accumulators -> smem (reshuffle for cell layout) ----
#pragma unroll
        for (int s = 0; s < 2; ++s) {
            int col = wn * 16 + s * 8 + 2 * t_id;
            int row = wm * 16 + g_id;
            g_sm[row * 33 + col]           = acc[s][0];
            g_sm[row * 33 + col + 1]       = acc[s][1];
            g_sm[(row + 8) * 33 + col]     = acc[s][2];
            g_sm[(row + 8) * 33 + col + 1] = acc[s][3];
        }
        __syncthreads();

        // ---- fused cell update ----
#pragma unroll
        for (int q = 0; q < 2; ++q) {
            int e = tid + q * 256;
            int b = e >> 3, jj = e & 7;
            float iv = g_sm[b * 33 + jj]       + xg[q][0];
            float fv = g_sm[b * 33 + 8 + jj]   + xg[q][1];
            float gv = g_sm[b * 33 + 16 + jj]  + xg[q][2];
            float ov = g_sm[b * 33 + 24 + jj]  + xg[q][3];
            iv = sigmoidf_(iv);
            fv = sigmoidf_(fv);
            gv = tanhf(gv);
            ov = sigmoidf_(ov);
            float cn = fv * c_reg[q] + iv * gv;
            c_reg[q] = cn;
            out[((size_t)t * BB + b) * HH + j0 + jj] = ov * tanhf(cn);
        }

        // ---- publish h_t: fence-all, then one arrival per block ----
        __threadfence();
        __syncthreads();
        if (tid == 0) atomicAdd(&g_bar, 1u);

        // ---- prefetch x_gates for t+1 while barrier settles ----
        if (t + 1 < TT) {
#pragma unroll
            for (int q = 0; q < 2; ++q) {
                int e = tid + q * 256;
                int b = e >> 3, jj = e & 7;
                const float* p = g_xg + ((size_t)(t + 1) * BB + b) * G4 + j0 + jj;
#pragma unroll
                for (int g = 0; g < 4; ++g) xg[q][g] = p[g * HH];
            }
        }
        // also prepare next g_sm usage: sync before anyone re-stages h into h_s
        // (the t>0 barrier + syncthreads at loop top provides this)
    }
}

// ---------------------------------------------------------------------------
// Launch
// ---------------------------------------------------------------------------
extern "C" void kernel_launch(void* const* d_in, const int* in_sizes, int n_in,
                              void* d_out, int out_size) {
    const float* inputs = (const float*)d_in[0];  // [T,B,I]
    const float* h0     = (const float*)d_in[1];  // [B,H]
    const float* c0     = (const float*)d_in[2];  // [B,H]
    const float* W_ih   = (const float*)d_in[3];  // [4H,I]
    const float* W_hh   = (const float*)d_in[4];  // [4H,H]
    const float* b_ih   = (const float*)d_in[5];  // [4H]
    const float* b_hh   = (const float*)d_in[6];  // [4H]
    float* out = (float*)d_out;                   // [T,B,H]

    cudaFuncSetAttribute(lstm_persistent,
                         cudaFuncAttributeMaxDynamicSharedMemorySize,
                         SMEM_WORDS * 4);

    init_kernel<<<1, 32>>>();
    xgates_kernel<<<dim3(63, 512), 256>>>(inputs, W_ih, b_ih, b_hh);
    lstm_persistent<<<NBLK, 256, SMEM_WORDS * 4>>>(h0, c0, W_hh, out);
}

// round 4
// speedup vs baseline: 1.2993x; 1.2993x over previous
#include <cuda_runtime.h>
#include <cuda_bf16.h>
#include <math.h>

// Problem constants
#define TT 512
#define BB 64
#define II 300
#define HH 1000
#define G4 4000   // 4*H
#define NBLK 125  // persistent blocks (125 <= 148 SMs -> all co-resident)

// ---------------------------------------------------------------------------
// Device scratch (allocation-free: __device__ globals)
// ---------------------------------------------------------------------------
__device__ float g_xg[(size_t)TT * BB * G4];  // precomputed input gates [T,B,4H]
__device__ unsigned g_slot[128];              // per-block arrival slots (no atomics)

// ---------------------------------------------------------------------------
// tf32 helpers
// ---------------------------------------------------------------------------
__device__ __forceinline__ unsigned f2tf32(float x) {
    unsigned y;
    asm("cvt.rna.tf32.f32 %0, %1;" : "=r"(y) : "f"(x));
    return y;
}

__device__ __forceinline__ void mma_tf32(float c[4], const unsigned a[4],
                                         unsigned b0, unsigned b1) {
    asm volatile(
        "mma.sync.aligned.m16n8k8.row.col.f32.tf32.tf32.f32 "
        "{%0,%1,%2,%3}, {%4,%5,%6,%7}, {%8,%9}, {%0,%1,%2,%3};"
        : "+f"(c[0]), "+f"(c[1]), "+f"(c[2]), "+f"(c[3])
        : "r"(a[0]), "r"(a[1]), "r"(a[2]), "r"(a[3]), "r"(b0), "r"(b1));
}

__device__ __forceinline__ float sigmoidf_(float x) {
    return 1.0f / (1.0f + __expf(-x));
}
__device__ __forceinline__ float tanhf_(float x) {
    return 2.0f / (1.0f + __expf(-2.0f * x)) - 1.0f;
}

// ---------------------------------------------------------------------------
// Kernel 1: x_gates = inputs @ W_ih^T + (b_ih + b_hh)  (+ barrier-slot reset)
// ---------------------------------------------------------------------------
__global__ void __launch_bounds__(256) xgates_kernel(
    const float* __restrict__ X, const float* __restrict__ Wih,
    const float* __restrict__ b_ih, const float* __restrict__ b_hh)
{
    if (blockIdx.x == 0 && blockIdx.y == 0 && threadIdx.x < 128)
        g_slot[threadIdx.x] = 0u;   // reset once per replay; visible at next launch

    const int m0 = blockIdx.y * 64;
    const int n0 = blockIdx.x * 64;
    const int tid  = threadIdx.x;
    const int lane = tid & 31;
    const int warp = tid >> 5;
    const int wm = warp & 3;
    const int wn = warp >> 2;

    __shared__ unsigned a_s[64][17];
    __shared__ unsigned b_s[64][17];

    float acc[4][4];
#pragma unroll
    for (int s = 0; s < 4; ++s)
#pragma unroll
        for (int i = 0; i < 4; ++i) acc[s][i] = 0.0f;

    const int g_id = lane >> 2;
    const int t_id = lane & 3;

    for (int ch = 0; ch < 19; ++ch) {
        const int k0 = ch * 16;
#pragma unroll
        for (int it = 0; it < 4; ++it) {
            int i = tid + it * 256;
            int m = i >> 4, k = i & 15;
            float va = (k0 + k < II) ? X[(size_t)(m0 + m) * II + k0 + k] : 0.0f;
            a_s[m][k] = f2tf32(va);
            int r = n0 + m;
            float vb = (r < G4 && k0 + k < II) ? Wih[(size_t)r * II + k0 + k] : 0.0f;
            b_s[m][k] = f2tf32(vb);
        }
        __syncthreads();

#pragma unroll
        for (int kk = 0; kk < 2; ++kk) {
            const int kb = kk * 8;
            unsigned a[4];
            a[0] = a_s[wm * 16 + g_id][kb + t_id];
            a[1] = a_s[wm * 16 + g_id + 8][kb + t_id];
            a[2] = a_s[wm * 16 + g_id][kb + t_id + 4];
            a[3] = a_s[wm * 16 + g_id + 8][kb + t_id + 4];
#pragma unroll
            for (int s = 0; s < 4; ++s) {
                unsigned b0 = b_s[wn * 32 + s * 8 + g_id][kb + t_id];
                unsigned b1 = b_s[wn * 32 + s * 8 + g_id][kb + t_id + 4];
                mma_tf32(acc[s], a, b0, b1);
            }
        }
        __syncthreads();
    }

#pragma unroll
    for (int s = 0; s < 4; ++s) {
        int n = n0 + wn * 32 + s * 8 + 2 * t_id;
        int row = m0 + wm * 16 + g_id;
        if (n < G4) {
            float bia0 = b_ih[n] + b_hh[n];
            float bia1 = b_ih[n + 1] + b_hh[n + 1];
            g_xg[(size_t)row * G4 + n]           = acc[s][0] + bia0;
            g_xg[(size_t)row * G4 + n + 1]       = acc[s][1] + bia1;
            g_xg[(size_t)(row + 8) * G4 + n]     = acc[s][2] + bia0;
            g_xg[(size_t)(row + 8) * G4 + n + 1] = acc[s][3] + bia1;
        }
    }
}

// ---------------------------------------------------------------------------
// Kernel 2: persistent LSTM. 125 blocks x 256 threads (8 warps).
//   Block owns 8 h-columns = 32 gate-major rows of W_hh (resident smem, tf32,
//   K zero-padded to 1024). Warp (wk=warp&3, wm=warp>>2) computes the m-half
//   wm (32 batch rows) x all 32 N-cols over K-slice [wk*256, wk*256+256):
//   warp-PRIVATE A staging (no __syncthreads in K loop), distance-2 LDG
//   prefetch, cross-warp K-reduction in smem, fused cell update, slot barrier.
// ---------------------------------------------------------------------------
// smem words:
//   W_s   : 32 * 1028          (1028 % 32 == 4 -> B-frag LDS conflict-free)
//   A_s   : 8 * 2 * 32 * 20    (20-stride: A-frag LDS conflict-free)
//   g_red : 256 * 36 floats
#define WS_STRIDE 1028
#define AS_STRIDE 20
#define AS_BUF (32 * AS_STRIDE)
#define SMEM_WORDS (32 * WS_STRIDE + 8 * 2 * AS_BUF + 256 * 36)

__global__ void __launch_bounds__(256, 1) lstm_persistent(
    const float* __restrict__ h0, const float* __restrict__ c0,
    const float* __restrict__ Whh, float* __restrict__ out)
{
    extern __shared__ unsigned sm[];
    unsigned* W_s   = sm;                                      // [32][1028]
    unsigned* A_s   = sm + 32 * WS_STRIDE;                     // [8][2][32][20]
    float*    g_red = (float*)(sm + 32 * WS_STRIDE + 8 * 2 * AS_BUF); // [256][36]

    const int bid  = blockIdx.x;
    const int j0   = bid * 8;
    const int tid  = threadIdx.x;
    const int lane = tid & 31;
    const int warp = tid >> 5;
    const int wk = warp & 3;       // K-slice [wk*256, +256)
    const int wm = warp >> 2;      // m-half: batch rows wm*32 .. +31
    const int g_id = lane >> 2;
    const int t_id = lane & 3;

    // ---- load W_hh slice (32 gate-major rows x 1024, zero-padded) once ----
    for (int idx = tid; idx < 32 * 1024; idx += 256) {
        int r = idx >> 10, k = idx & 1023;
        int row = (r >> 3) * HH + j0 + (r & 7);
        float v = (k < HH) ? Whh[(size_t)row * HH + k] : 0.0f;
        W_s[r * WS_STRIDE + k] = f2tf32(v);
    }

    // ---- cell state in registers (2 cells/thread) ----
    float c_reg[2];
#pragma unroll
    for (int q = 0; q < 2; ++q) {
        int e = tid + q * 256;
        c_reg[q] = c0[(e >> 3) * HH + j0 + (e & 7)];
    }

    // ---- prefetch x_gates for t=0 ----
    float xg[2][4];
#pragma unroll
    for (int q = 0; q < 2; ++q) {
        int e = tid + q * 256;
        const float* p = g_xg + (size_t)(e >> 3) * G4 + j0 + (e & 7);
#pragma unroll
        for (int g = 0; g < 4; ++g) xg[q][g] = p[g * HH];
    }

    __syncthreads();

    unsigned* Aw = A_s + warp * (2 * AS_BUF);
    const int K0   = wk * 256;
    const int arow = lane & 7;          // staging row within each 8-row group
    const int akq  = (lane >> 3) * 4;   // staging k offset {0,4,8,12}

    for (int t = 0; t < TT; ++t) {
        // ---- slot barrier: wait for h_{t-1} from all blocks ----
        if (t > 0) {
            if (warp == 0) {
                const unsigned tgt = (unsigned)t;
                for (;;) {
                    bool ok = true;
#pragma unroll
                    for (int s = 0; s < 4; ++s) {
                        int id = lane + 32 * s;
                        if (id < NBLK)
                            ok &= (*(volatile unsigned*)&g_slot[id] >= tgt);
                    }
                    if (__ballot_sync(0xffffffffu, ok) == 0xffffffffu) break;
                }
                __threadfence();   // acquire: order h loads after slot observation
            }
            __syncthreads();
        }
        const float* hp    = (t == 0) ? h0 : out + (size_t)(t - 1) * BB * HH;
        const float* hbase = hp + (size_t)wm * 32 * HH;

        float acc[2][4][4];
#pragma unroll
        for (int mt = 0; mt < 2; ++mt)
#pragma unroll
            for (int nt = 0; nt < 4; ++nt)
#pragma unroll
                for (int i = 0; i < 4; ++i) acc[mt][nt][i] = 0.0f;

        float4 stg[2][4];   // two in-flight LDG sets (4 rows x 16B each)

        auto LDGC = [&](float4* s, int ch) {
            const int kb = K0 + ch * 16;
            if (kb + 16 <= HH) {
#pragma unroll
                for (int i = 0; i < 4; ++i)
                    s[i] = *(const float4*)&hbase[(size_t)(i * 8 + arow) * HH + kb + akq];
            } else {
#pragma unroll
                for (int i = 0; i < 4; ++i) {
                    const float* rb = &hbase[(size_t)(i * 8 + arow) * HH];
                    int kg = kb + akq;
                    float v0 = (kg + 0 < HH) ? rb[kg + 0] : 0.0f;
                    float v1 = (kg + 1 < HH) ? rb[kg + 1] : 0.0f;
                    float v2 = (kg + 2 < HH) ? rb[kg + 2] : 0.0f;
                    float v3 = (kg + 3 < HH) ? rb[kg + 3] : 0.0f;
                    s[i] = make_float4(v0, v1, v2, v3);
                }
            }
        };
        auto STSC = [&](const float4* s, unsigned* buf) {
#pragma unroll
            for (int i = 0; i < 4; ++i) {
                uint4 u;
                u.x = f2tf32(s[i].x); u.y = f2tf32(s[i].y);
                u.z = f2tf32(s[i].z); u.w = f2tf32(s[i].w);
                *(uint4*)&buf[(i * 8 + arow) * AS_STRIDE + akq] = u;
            }
        };
        auto COMP = [&](const unsigned* buf, int ch) {
#pragma unroll
            for (int kk = 0; kk < 2; ++kk) {
                const int kb = kk * 8;
                unsigned a[2][4];
#pragma unroll
                for (int mt = 0; mt < 2; ++mt) {
                    a[mt][0] = buf[(mt * 16 + g_id) * AS_STRIDE + kb + t_id];
                    a[mt][1] = buf[(mt * 16 + g_id + 8) * AS_STRIDE + kb + t_id];
                    a[mt][2] = buf[(mt * 16 + g_id) * AS_STRIDE + kb + t_id + 4];
                    a[mt][3] = buf[(mt * 16 + g_id + 8) * AS_STRIDE + kb + t_id + 4];
                }
                const int wkoff = K0 + ch * 16 + kb;
#pragma unroll
                for (int nt = 0; nt < 4; ++nt) {
                    unsigned b0 = W_s[(nt * 8 + g_id) * WS_STRIDE + wkoff + t_id];
                    unsigned b1 = W_s[(nt * 8 + g_id) * WS_STRIDE + wkoff + t_id + 4];
                    mma_tf32(acc[0][nt], a[0], b0, b1);
                    mma_tf32(acc[1][nt], a[1], b0, b1);
                }
            }
        };

        // ---- warp-private pipelined K loop: 16 chunks of 16 k ----
        LDGC(stg[0], 0);
        LDGC(stg[1], 1);
        STSC(stg[0], Aw);
        __syncwarp();
#pragma unroll 4
        for (int ch = 0; ch < 16; ++ch) {
            if (ch + 2 < 16) LDGC(stg[ch & 1], ch + 2);
            COMP(Aw + (ch & 1) * AS_BUF, ch);
            if (ch + 1 < 16) {
                STSC(stg[(ch + 1) & 1], Aw + ((ch + 1) & 1) * AS_BUF);
                __syncwarp();
            }
        }

        // ---- dump partial accumulators ----
        {
            float* myred = g_red + (size_t)tid * 36;
#pragma unroll
            for (int mt = 0; mt < 2; ++mt)
#pragma unroll
                for (int nt = 0; nt < 4; ++nt)
                    *(float4*)&myred[(mt * 4 + nt) * 4] =
                        make_float4(acc[mt][nt][0], acc[mt][nt][1],
                                    acc[mt][nt][2], acc[mt][nt][3]);
        }
        __syncthreads();

        // ---- K-reduction (over 4 wk warps) + fused cell update ----
#pragma unroll
        for (int q = 0; q < 2; ++q) {
            int e = tid + q * 256;
            int b = e >> 3, jj = e & 7;
            int wmh  = b >> 5;           // which m-half
            int mloc = b & 31;
            int mt = mloc >> 4, r = mloc & 15;
            int lane_ = (r & 7) * 4 + (jj >> 1);
            int qidx  = (r >> 3) * 2 + (jj & 1);
            float gv[4];
#pragma unroll
            for (int g = 0; g < 4; ++g) {
                float s = 0.0f;
#pragma unroll
                for (int k = 0; k < 4; ++k) {
                    int w = wmh * 4 + k;
                    s += g_red[(size_t)(w * 32 + lane_) * 36 + (mt * 4 + g) * 4 + qidx];
                }
                gv[g] = s + xg[q][g];
            }
            float iv = sigmoidf_(gv[0]);
            float fv = sigmoidf_(gv[1]);
            float gg = tanhf_(gv[2]);
            float ov = sigmoidf_(gv[3]);
            float cn = fv * c_reg[q] + iv * gg;
            c_reg[q] = cn;
            out[((size_t)t * BB + b) * HH + j0 + jj] = ov * tanhf_(cn);
        }

        // ---- publish h_t: per-thread fence, block sync, single slot store ----
        __threadfence();
        __syncthreads();
        if (tid == 0) *(volatile unsigned*)&g_slot[bid] = (unsigned)(t + 1);

        // ---- prefetch x_gates for t+1 while others finish ----
        if (t + 1 < TT) {
#pragma unroll
            for (int q = 0; q < 2; ++q) {
                int e = tid + q * 256;
                const float* p = g_xg + ((size_t)(t + 1) * BB + (e >> 3)) * G4 + j0 + (e & 7);
#pragma unroll
                for (int g = 0; g < 4; ++g) xg[q][g] = p[g * HH];
            }
        }
    }
}

// ---------------------------------------------------------------------------
// Launch
// ---------------------------------------------------------------------------
extern "C" void kernel_launch(void* const* d_in, const int* in_sizes, int n_in,
                              void* d_out, int out_size) {
    const float* inputs = (const float*)d_in[0];  // [T,B,I]
    const float* h0     = (const float*)d_in[1];  // [B,H]
    const float* c0     = (const float*)d_in[2];  // [B,H]
    const float* W_ih   = (const float*)d_in[3];  // [4H,I]
    const float* W_hh   = (const float*)d_in[4];  // [4H,H]
    const float* b_ih   = (const float*)d_in[5];  // [4H]
    const float* b_hh   = (const float*)d_in[6];  // [4H]
    float* out = (float*)d_out;                   // [T,B,H]

    cudaFuncSetAttribute(lstm_persistent,
                         cudaFuncAttributeMaxDynamicSharedMemorySize,
                         SMEM_WORDS * 4);

    xgates_kernel<<<dim3(63, 512), 256>>>(inputs, W_ih, b_ih, b_hh);
    lstm_persistent<<<NBLK, 256, SMEM_WORDS * 4>>>(h0, c0, W_hh, out);
}

// round 6
// speedup vs baseline: 1.6722x; 1.2870x over previous
#include <cuda_runtime.h>
#include <cuda_bf16.h>
#include <cuda_pipeline.h>
#include <cstdint>
#include <math.h>

// Problem constants
#define TT 512
#define BB 64
#define II 300
#define HH 1000
#define G4 4000
#define KP 1024           // padded K
#define NBLK 125          // persistent blocks (<=148 SMs -> co-resident)

// ---------------------------------------------------------------------------
// Device scratch (allocation-free: __device__ globals)
// ---------------------------------------------------------------------------
__device__ float g_xg[(size_t)TT * BB * G4];  // x_gates [T,B,4H]
__device__ unsigned g_h[BB * KP];             // h in tf32 bits, k-padded (bss zero)
__device__ unsigned g_slot[128];              // per-block step slots

// ---------------------------------------------------------------------------
// helpers
// ---------------------------------------------------------------------------
__device__ __forceinline__ unsigned f2tf32(float x) {
    unsigned y;
    asm("cvt.rna.tf32.f32 %0, %1;" : "=r"(y) : "f"(x));
    return y;
}
__device__ __forceinline__ void mma_tf32(float c[4], const unsigned a[4],
                                         unsigned b0, unsigned b1) {
    asm volatile(
        "mma.sync.aligned.m16n8k8.row.col.f32.tf32.tf32.f32 "
        "{%0,%1,%2,%3}, {%4,%5,%6,%7}, {%8,%9}, {%0,%1,%2,%3};"
        : "+f"(c[0]), "+f"(c[1]), "+f"(c[2]), "+f"(c[3])
        : "r"(a[0]), "r"(a[1]), "r"(a[2]), "r"(a[3]), "r"(b0), "r"(b1));
}
__device__ __forceinline__ float sigmoidf_(float x) { return 1.0f / (1.0f + __expf(-x)); }
__device__ __forceinline__ float tanhf_(float x) { return 2.0f / (1.0f + __expf(-2.0f * x)) - 1.0f; }

// ---------------------------------------------------------------------------
// Kernel 1: x_gates = inputs @ W_ih^T + (b_ih + b_hh)
//           + slot reset + g_h pad-zero (block 0,0)
// ---------------------------------------------------------------------------
__global__ void __launch_bounds__(256) xgates_kernel(
    const float* __restrict__ X, const float* __restrict__ Wih,
    const float* __restrict__ b_ih, const float* __restrict__ b_hh)
{
    if (blockIdx.x == 0 && blockIdx.y == 0) {
        if (threadIdx.x < 128) g_slot[threadIdx.x] = 0u;
        for (int i = threadIdx.x; i < BB * (KP - HH); i += 256) {
            int r = i / (KP - HH), p = i % (KP - HH);
            g_h[r * KP + HH + p] = 0u;
        }
    }

    const int m0 = blockIdx.y * 64;
    const int n0 = blockIdx.x * 64;
    const int tid  = threadIdx.x;
    const int lane = tid & 31;
    const int warp = tid >> 5;
    const int wm = warp & 3;
    const int wn = warp >> 2;

    __shared__ unsigned a_s[64][17];
    __shared__ unsigned b_s[64][17];

    float acc[4][4];
#pragma unroll
    for (int s = 0; s < 4; ++s)
#pragma unroll
        for (int i = 0; i < 4; ++i) acc[s][i] = 0.0f;

    const int g_id = lane >> 2;
    const int t_id = lane & 3;

    for (int ch = 0; ch < 19; ++ch) {
        const int k0 = ch * 16;
#pragma unroll
        for (int it = 0; it < 4; ++it) {
            int i = tid + it * 256;
            int m = i >> 4, k = i & 15;
            float va = (k0 + k < II) ? X[(size_t)(m0 + m) * II + k0 + k] : 0.0f;
            a_s[m][k] = f2tf32(va);
            int r = n0 + m;
            float vb = (r < G4 && k0 + k < II) ? Wih[(size_t)r * II + k0 + k] : 0.0f;
            b_s[m][k] = f2tf32(vb);
        }
        __syncthreads();

#pragma unroll
        for (int kk = 0; kk < 2; ++kk) {
            const int kb = kk * 8;
            unsigned a[4];
            a[0] = a_s[wm * 16 + g_id][kb + t_id];
            a[1] = a_s[wm * 16 + g_id + 8][kb + t_id];
            a[2] = a_s[wm * 16 + g_id][kb + t_id + 4];
            a[3] = a_s[wm * 16 + g_id + 8][kb + t_id + 4];
#pragma unroll
            for (int s = 0; s < 4; ++s) {
                unsigned b0 = b_s[wn * 32 + s * 8 + g_id][kb + t_id];
                unsigned b1 = b_s[wn * 32 + s * 8 + g_id][kb + t_id + 4];
                mma_tf32(acc[s], a, b0, b1);
            }
        }
        __syncthreads();
    }

#pragma unroll
    for (int s = 0; s < 4; ++s) {
        int n = n0 + wn * 32 + s * 8 + 2 * t_id;
        int row = m0 + wm * 16 + g_id;
        if (n < G4) {
            float bia0 = b_ih[n] + b_hh[n];
            float bia1 = b_ih[n + 1] + b_hh[n + 1];
            g_xg[(size_t)row * G4 + n]           = acc[s][0] + bia0;
            g_xg[(size_t)row * G4 + n + 1]       = acc[s][1] + bia1;
            g_xg[(size_t)(row + 8) * G4 + n]     = acc[s][2] + bia0;
            g_xg[(size_t)(row + 8) * G4 + n + 1] = acc[s][3] + bia1;
        }
    }
}

// ---------------------------------------------------------------------------
// Kernel 2: persistent LSTM, 125 blocks x 512 threads (16 warps).
//   Block owns 8 h-cols (32 gate-major W rows resident in smem, K padded 1024).
//   Per step: 8 chunks of k128 staged via cp.async from g_h (pre-tf32) into
//   double-buffered smem; warp (wk=warp&7, wm=warp>>3) computes m32 x n32 on
//   its k16 slice of each chunk; 8-way K reduction in smem; fused cell update;
//   h_t -> out (fp32) and g_h (tf32); slot barrier.
// ---------------------------------------------------------------------------
#define WS_STRIDE 1028              // 1028 % 32 == 4 -> B-frag conflict-free
#define AS_STRIDE 132               // 132 % 32 == 4  -> A-frag conflict-free
#define AS_WORDS (64 * AS_STRIDE)   // 8448 words per buffer
#define W_WORDS (32 * WS_STRIDE)    // 32896 words
#define SMEM_WORDS (W_WORDS + 2 * AS_WORDS)
#define RED_STRIDE 33               // reduction scratch reuses both A buffers

__global__ void __launch_bounds__(512, 1) lstm_persistent(
    const float* __restrict__ h0, const float* __restrict__ c0,
    const float* __restrict__ Whh, float* __restrict__ out)
{
    extern __shared__ unsigned sm[];
    unsigned* W_s  = sm;                       // [32][1028]
    unsigned* bufA[2] = { sm + W_WORDS, sm + W_WORDS + AS_WORDS };
    float*    red  = (float*)(sm + W_WORDS);   // [16*32][33] (reuses A bufs)

    const int bid  = blockIdx.x;
    const int j0   = bid * 8;
    const int tid  = threadIdx.x;
    const int lane = tid & 31;
    const int warp = tid >> 5;
    const int wk = warp & 7;        // k16 slice within each k128 chunk
    const int wm = warp >> 3;       // m-half (32 batch rows)
    const int g_id = lane >> 2;
    const int t_id = lane & 3;

    // ---- resident W: 32 gate-major rows x 1024 k (zero-padded), tf32 ----
    for (int idx = tid; idx < 32 * KP; idx += 512) {
        int n = idx >> 10, k = idx & (KP - 1);
        int row = (n >> 3) * HH + j0 + (n & 7);
        float v = (k < HH) ? Whh[(size_t)row * HH + k] : 0.0f;
        W_s[n * WS_STRIDE + k] = f2tf32(v);
    }

    // ---- per-thread cell state + xg prefetch (1 cell/thread: b=tid>>3, jj=tid&7)
    const int eb = tid >> 3, ej = tid & 7;
    float c_reg = c0[eb * HH + j0 + ej];
    float xg[4];
    {
        const float* p = g_xg + (size_t)eb * G4 + j0 + ej;
#pragma unroll
        for (int g = 0; g < 4; ++g) xg[g] = p[g * HH];
    }
    __syncthreads();

    // staging assignment: thread -> row sr (8 thr/row), 16-word segment ss
    const int sr = tid >> 3;
    const int ss = (tid & 7) * 16;

    for (int t = 0; t < TT; ++t) {
        // ---- slot barrier: wait for h_{t-1} (g_h) from all blocks ----
        if (t > 0) {
            if (warp == 0) {
                const unsigned tgt = (unsigned)t;
                for (;;) {
                    bool ok = true;
#pragma unroll
                    for (int s = 0; s < 4; ++s) {
                        int id = lane + 32 * s;
                        if (id < NBLK) ok &= (*(volatile unsigned*)&g_slot[id] >= tgt);
                    }
                    if (__ballot_sync(0xffffffffu, ok) == 0xffffffffu) break;
                }
                __threadfence();
            }
            __syncthreads();
        }

        // stage one k128 chunk into a buffer
        auto stage = [&](int bsel, int ch) {
            unsigned* dst = bufA[bsel] + sr * AS_STRIDE + ss;
            if (t == 0) {
#pragma unroll
                for (int j = 0; j < 16; ++j) {
                    int k = ch * 128 + ss + j;
                    dst[j] = f2tf32((k < HH) ? h0[sr * HH + k] : 0.0f);
                }
            } else {
                const unsigned* src = g_h + sr * KP + ch * 128 + ss;
#pragma unroll
                for (int q = 0; q < 4; ++q)
                    __pipeline_memcpy_async(dst + q * 4, src + q * 4, 16);
                __pipeline_commit();
            }
        };

        float acc[2][4][4];
#pragma unroll
        for (int mt = 0; mt < 2; ++mt)
#pragma unroll
            for (int nt = 0; nt < 4; ++nt)
#pragma unroll
                for (int i = 0; i < 4; ++i) acc[mt][nt][i] = 0.0f;

        // compute this warp's k16 slice of one staged chunk
        auto compute = [&](const unsigned* buf, int ch) {
#pragma unroll
            for (int kk = 0; kk < 2; ++kk) {
                const int ko = wk * 16 + kk * 8;
                unsigned a[2][4];
#pragma unroll
                for (int mt = 0; mt < 2; ++mt) {
                    const unsigned* ab = buf + (wm * 32 + mt * 16) * AS_STRIDE + ko;
                    a[mt][0] = ab[g_id * AS_STRIDE + t_id];
                    a[mt][1] = ab[(g_id + 8) * AS_STRIDE + t_id];
                    a[mt][2] = ab[g_id * AS_STRIDE + t_id + 4];
                    a[mt][3] = ab[(g_id + 8) * AS_STRIDE + t_id + 4];
                }
                const int kg = ch * 128 + ko;
#pragma unroll
                for (int nt = 0; nt < 4; ++nt) {
                    unsigned b0 = W_s[(nt * 8 + g_id) * WS_STRIDE + kg + t_id];
                    unsigned b1 = W_s[(nt * 8 + g_id) * WS_STRIDE + kg + t_id + 4];
                    mma_tf32(acc[0][nt], a[0], b0, b1);
                    mma_tf32(acc[1][nt], a[1], b0, b1);
                }
            }
        };

        // ---- pipelined chunk loop: 8 chunks of k128, double-buffered ----
        stage(0, 0);
        stage(1, 1);
        __pipeline_wait_prior(1);
        __syncthreads();
#pragma unroll
        for (int ch = 0; ch < 8; ++ch) {
            compute(bufA[ch & 1], ch);
            __syncthreads();                    // all warps done reading this buf
            if (ch < 6) {
                stage(ch & 1, ch + 2);
                __pipeline_wait_prior(1);       // chunk ch+1 resident
                __syncthreads();
            } else if (ch == 6) {
                __pipeline_wait_prior(0);       // chunk 7 resident
                __syncthreads();
            }
        }

        // ---- dump partials (reduction scratch overlays A buffers) ----
        {
            float* my = red + (size_t)tid * RED_STRIDE;
#pragma unroll
            for (int mt = 0; mt < 2; ++mt)
#pragma unroll
                for (int nt = 0; nt < 4; ++nt)
#pragma unroll
                    for (int v = 0; v < 4; ++v)
                        my[(mt * 4 + nt) * 4 + v] = acc[mt][nt][v];
        }
        __syncthreads();

        // ---- 8-way K reduction + fused cell update (1 cell/thread) ----
        {
            const int wmh  = eb >> 5;
            const int mt   = (eb >> 4) & 1;
            const int lane_ = (eb & 7) * 4 + (ej >> 1);
            const int v    = ((eb >> 3) & 1) * 2 + (ej & 1);
            float gv[4];
#pragma unroll
            for (int g = 0; g < 4; ++g) {
                const int i = (mt * 4 + g) * 4 + v;
                float s = 0.0f;
#pragma unroll
                for (int k = 0; k < 8; ++k)
                    s += red[(size_t)((wmh * 8 + k) * 32 + lane_) * RED_STRIDE + i];
                gv[g] = s + xg[g];
            }
            float iv = sigmoidf_(gv[0]);
            float fv = sigmoidf_(gv[1]);
            float gg = tanhf_(gv[2]);
            float ov = sigmoidf_(gv[3]);
            float cn = fv * c_reg + iv * gg;
            c_reg = cn;
            float hn = ov * tanhf_(cn);
            out[((size_t)t * BB + eb) * HH + j0 + ej] = hn;
            g_h[eb * KP + j0 + ej] = f2tf32(hn);
        }

        // ---- publish ----
        __threadfence();
        __syncthreads();
        if (tid == 0) *(volatile unsigned*)&g_slot[bid] = (unsigned)(t + 1);

        // ---- prefetch x_gates for t+1 ----
        if (t + 1 < TT) {
            const float* p = g_xg + ((size_t)(t + 1) * BB + eb) * G4 + j0 + ej;
#pragma unroll
            for (int g = 0; g < 4; ++g) xg[g] = p[g * HH];
        }
    }
}

// ---------------------------------------------------------------------------
// Launch
// ---------------------------------------------------------------------------
extern "C" void kernel_launch(void* const* d_in, const int* in_sizes, int n_in,
                              void* d_out, int out_size) {
    const float* inputs = (const float*)d_in[0];
    const float* h0     = (const float*)d_in[1];
    const float* c0     = (const float*)d_in[2];
    const float* W_ih   = (const float*)d_in[3];
    const float* W_hh   = (const float*)d_in[4];
    const float* b_ih   = (const float*)d_in[5];
    const float* b_hh   = (const float*)d_in[6];
    float* out = (float*)d_out;

    cudaFuncSetAttribute(lstm_persistent,
                         cudaFuncAttributeMaxDynamicSharedMemorySize,
                         SMEM_WORDS * 4);

    xgates_kernel<<<dim3(63, 512), 256>>>(inputs, W_ih, b_ih, b_hh);
    lstm_persistent<<<NBLK, 512, SMEM_WORDS * 4>>>(h0, c0, W_hh, out);
}

// round 11
// speedup vs baseline: 2.6955x; 1.6119x over previous
#include <cuda_runtime.h>
#include <cuda_bf16.h>
#include <cstdint>
#include <math.h>

// Problem constants
#define TT 512
#define BB 64
#define II 300
#define HH 1000
#define G4 4000
#define KP 1024           // padded K
#define NBLK 125          // persistent blocks (<=148 SMs -> co-resident)

// ---------------------------------------------------------------------------
// Device scratch (allocation-free: __device__ globals)
// ---------------------------------------------------------------------------
__device__ float g_xg[(size_t)TT * BB * G4];   // x_gates [T,B,4H]
__device__ unsigned g_hf[2][BB * KP];          // h as tf32 MMA fragments, 2 parities
__device__ unsigned g_slot[128];               // per-block step slots

// ---------------------------------------------------------------------------
// helpers
// ---------------------------------------------------------------------------
__device__ __forceinline__ unsigned f2tf32(float x) {
    unsigned y;
    asm("cvt.rna.tf32.f32 %0, %1;" : "=r"(y) : "f"(x));
    return y;
}
__device__ __forceinline__ void mma_tf32(float c[4], unsigned a0, unsigned a1,
                                         unsigned a2, unsigned a3,
                                         unsigned b0, unsigned b1) {
    asm volatile(
        "mma.sync.aligned.m16n8k8.row.col.f32.tf32.tf32.f32 "
        "{%0,%1,%2,%3}, {%4,%5,%6,%7}, {%8,%9}, {%0,%1,%2,%3};"
        : "+f"(c[0]), "+f"(c[1]), "+f"(c[2]), "+f"(c[3])
        : "r"(a0), "r"(a1), "r"(a2), "r"(a3), "r"(b0), "r"(b1));
}
__device__ __forceinline__ float sigmoidf_(float x) { return 1.0f / (1.0f + __expf(-x)); }
__device__ __forceinline__ float tanhf_(float x) { return 2.0f / (1.0f + __expf(-2.0f * x)) - 1.0f; }

// Fragment-order address (in words) of A element (b, kglob):
//   warp tile (wm=b>>5, wk=(kglob&127)>>4), chunk ch=kglob>>7,
//   kk=(kglob>>3)&1, mt=(b>>4)&1, lane=(b&7)*4+(kglob&3),
//   quad q = ((b>>3)&1) + 2*((kglob>>2)&1)
__device__ __forceinline__ int frag_addr_of(int b, int kglob) {
    int wm = b >> 5, mt = (b >> 4) & 1, rsel = (b >> 3) & 1, gi = b & 7;
    int ch = kglob >> 7, r = kglob & 127;
    int wk = r >> 4, kk = (r >> 3) & 1, k3 = r & 7;
    int tl = k3 & 3, ksel = k3 >> 2;
    int lane = gi * 4 + tl;
    int q = rsel + 2 * ksel;
    int fragidx = ((((wm * 8 + wk) * 8 + ch) * 2 + kk) * 2 + mt);
    return fragidx * 128 + lane * 4 + q;
}

// ---------------------------------------------------------------------------
// Kernel 0: prep — h0 -> g_hf[0] fragments; reset slots
// ---------------------------------------------------------------------------
__global__ void __launch_bounds__(256) prep_kernel(const float* __restrict__ h0) {
    const int b = blockIdx.x;                 // 64 blocks
    if (b == 0 && threadIdx.x < 128) g_slot[threadIdx.x] = 0u;
    for (int k = threadIdx.x; k < HH; k += 256)
        g_hf[0][frag_addr_of(b, k)] = f2tf32(h0[b * HH + k]);
    // pad region (k >= 1000) of both parities is never written by anyone:
    // zero from module load, stays zero across replays.
}

// ---------------------------------------------------------------------------
// Kernel 1: x_gates = inputs @ W_ih^T + (b_ih + b_hh)
// ---------------------------------------------------------------------------
__global__ void __launch_bounds__(256) xgates_kernel(
    const float* __restrict__ X, const float* __restrict__ Wih,
    const float* __restrict__ b_ih, const float* __restrict__ b_hh)
{
    const int m0 = blockIdx.y * 64;
    const int n0 = blockIdx.x * 64;
    const int tid  = threadIdx.x;
    const int lane = tid & 31;
    const int warp = tid >> 5;
    const int wm = warp & 3;
    const int wn = warp >> 2;

    __shared__ unsigned a_s[64][17];
    __shared__ unsigned b_s[64][17];

    float acc[4][4];
#pragma unroll
    for (int s = 0; s < 4; ++s)
#pragma unroll
        for (int i = 0; i < 4; ++i) acc[s][i] = 0.0f;

    const int g_id = lane >> 2;
    const int t_id = lane & 3;

    for (int ch = 0; ch < 19; ++ch) {
        const int k0 = ch * 16;
#pragma unroll
        for (int it = 0; it < 4; ++it) {
            int i = tid + it * 256;
            int m = i >> 4, k = i & 15;
            float va = (k0 + k < II) ? X[(size_t)(m0 + m) * II + k0 + k] : 0.0f;
            a_s[m][k] = f2tf32(va);
            int r = n0 + m;
            float vb = (r < G4 && k0 + k < II) ? Wih[(size_t)r * II + k0 + k] : 0.0f;
            b_s[m][k] = f2tf32(vb);
        }
        __syncthreads();

#pragma unroll
        for (int kk = 0; kk < 2; ++kk) {
            const int kb = kk * 8;
            unsigned a[4];
            a[0] = a_s[wm * 16 + g_id][kb + t_id];
            a[1] = a_s[wm * 16 + g_id + 8][kb + t_id];
            a[2] = a_s[wm * 16 + g_id][kb + t_id + 4];
            a[3] = a_s[wm * 16 + g_id + 8][kb + t_id + 4];
#pragma unroll
            for (int s = 0; s < 4; ++s) {
                unsigned b0 = b_s[wn * 32 + s * 8 + g_id][kb + t_id];
                unsigned b1 = b_s[wn * 32 + s * 8 + g_id][kb + t_id + 4];
                mma_tf32(acc[s], a[0], a[1], a[2], a[3], b0, b1);
            }
        }
        __syncthreads();
    }

#pragma unroll
    for (int s = 0; s < 4; ++s) {
        int n = n0 + wn * 32 + s * 8 + 2 * t_id;
        int row = m0 + wm * 16 + g_id;
        if (n < G4) {
            float bia0 = b_ih[n] + b_hh[n];
            float bia1 = b_ih[n + 1] + b_hh[n + 1];
            g_xg[(size_t)row * G4 + n]           = acc[s][0] + bia0;
            g_xg[(size_t)row * G4 + n + 1]       = acc[s][1] + bia1;
            g_xg[(size_t)(row + 8) * G4 + n]     = acc[s][2] + bia0;
            g_xg[(size_t)(row + 8) * G4 + n + 1] = acc[s][3] + bia1;
        }
    }
}

// ---------------------------------------------------------------------------
// Kernel 2: persistent LSTM, 125 blocks x 512 threads (16 warps).
//   A (h) read DIRECTLY from fragment-ordered global g_hf[t&1] via coalesced
//   LDG.128 — no staging, no cp.async, no A smem. B = W_hh slice resident in
//   smem (tf32, K-padded 1024). Warp (wk=warp&7, wm=warp>>3): m32 x n32 on its
//   k16-per-chunk slice; 8-way K reduction in smem; fused cell update;
//   h_t scattered (1 STG/thread) into g_hf[(t+1)&1]; slot barrier.
// ---------------------------------------------------------------------------
#define WS_STRIDE 1028              // 1028 % 32 == 4 -> B-frag LDS conflict-free
#define W_WORDS (32 * WS_STRIDE)
#define RED_STRIDE 33
#define SMEM_WORDS (W_WORDS + 512 * RED_STRIDE)

__global__ void __launch_bounds__(512, 1) lstm_persistent(
    const float* __restrict__ c0, const float* __restrict__ Whh,
    float* __restrict__ out)
{
    extern __shared__ unsigned sm[];
    unsigned* W_s = sm;                         // [32][1028]
    float*    red = (float*)(sm + W_WORDS);     // [512][33]

    const int bid  = blockIdx.x;
    const int j0   = bid * 8;
    const int tid  = threadIdx.x;
    const int lane = tid & 31;
    const int warp = tid >> 5;
    const int wk = warp & 7;        // k16 slice within each k128 chunk
    const int wm = warp >> 3;       // m-half (32 batch rows)
    const int g_id = lane >> 2;
    const int t_id = lane & 3;

    // ---- resident W: 32 gate-major rows x 1024 k (zero-padded), tf32 ----
    for (int idx = tid; idx < 32 * KP; idx += 512) {
        int n = idx >> 10, k = idx & (KP - 1);
        int row = (n >> 3) * HH + j0 + (n & 7);
        float v = (k < HH) ? Whh[(size_t)row * HH + k] : 0.0f;
        W_s[n * WS_STRIDE + k] = f2tf32(v);
    }

    // ---- per-thread cell state + xg prefetch (1 cell: b=tid>>3, jj=tid&7) ----
    const int eb = tid >> 3, ej = tid & 7;
    float c_reg = c0[eb * HH + j0 + ej];
    float xg[4];
    {
        const float* p = g_xg + (size_t)eb * G4 + j0 + ej;
#pragma unroll
        for (int g = 0; g < 4; ++g) xg[g] = p[g * HH];
    }
    // epilogue scatter address (constant across steps, alternates parity)
    const int scat = frag_addr_of(eb, j0 + ej);
    __syncthreads();

    // per-warp fragment base (words): fragidx = (((wm*8+wk)*8+ch)*2+kk)*2+mt
    const int fbase = (wm * 8 + wk) * 8 * 4 * 128 + lane * 4;

    for (int t = 0; t < TT; ++t) {
        // ---- slot barrier: wait for all blocks to publish h_{t-1} ----
        if (t > 0) {
            if (warp == 0) {
                const unsigned tgt = (unsigned)t;
                for (;;) {
                    bool ok = true;
#pragma unroll
                    for (int s = 0; s < 4; ++s) {
                        int id = lane + 32 * s;
                        if (id < NBLK) ok &= (*(volatile unsigned*)&g_slot[id] >= tgt);
                    }
                    if (__ballot_sync(0xffffffffu, ok) == 0xffffffffu) break;
                }
                __threadfence();
            }
            __syncthreads();
        }
        const unsigned* Af = g_hf[t & 1];

        float acc[2][4][4];
#pragma unroll
        for (int mt = 0; mt < 2; ++mt)
#pragma unroll
            for (int nt = 0; nt < 4; ++nt)
#pragma unroll
                for (int i = 0; i < 4; ++i) acc[mt][nt][i] = 0.0f;

        // ---- K loop: 8 chunks; A via direct LDG.128, double-buffered ----
        uint4 av[2][2][2];   // [buf][kk][mt]
        {
            const uint4* p = (const uint4*)(Af + fbase);
#pragma unroll
            for (int kk = 0; kk < 2; ++kk)
#pragma unroll
                for (int mt = 0; mt < 2; ++mt)
                    av[0][kk][mt] = p[kk * 64 + mt * 32];   // (kk*2+mt)*128 words
        }
#pragma unroll
        for (int ch = 0; ch < 8; ++ch) {
            if (ch < 7) {
                const uint4* p = (const uint4*)(Af + fbase + (ch + 1) * 4 * 128);
#pragma unroll
                for (int kk = 0; kk < 2; ++kk)
#pragma unroll
                    for (int mt = 0; mt < 2; ++mt)
                        av[(ch + 1) & 1][kk][mt] = p[kk * 64 + mt * 32];
            }
            const uint4 (*a)[2] = av[ch & 1];
#pragma unroll
            for (int kk = 0; kk < 2; ++kk) {
                const int kg = ch * 128 + wk * 16 + kk * 8;
#pragma unroll
                for (int nt = 0; nt < 4; ++nt) {
                    unsigned b0 = W_s[(nt * 8 + g_id) * WS_STRIDE + kg + t_id];
                    unsigned b1 = W_s[(nt * 8 + g_id) * WS_STRIDE + kg + t_id + 4];
                    mma_tf32(acc[0][nt], a[kk][0].x, a[kk][0].y, a[kk][0].z, a[kk][0].w, b0, b1);
                    mma_tf32(acc[1][nt], a[kk][1].x, a[kk][1].y, a[kk][1].z, a[kk][1].w, b0, b1);
                }
            }
        }

        // ---- dump partials ----
        {
            float* my = red + (size_t)tid * RED_STRIDE;
#pragma unroll
            for (int mt = 0; mt < 2; ++mt)
#pragma unroll
                for (int nt = 0; nt < 4; ++nt)
#pragma unroll
                    for (int v = 0; v < 4; ++v)
                        my[(mt * 4 + nt) * 4 + v] = acc[mt][nt][v];
        }
        __syncthreads();

        // ---- 8-way K reduction + fused cell update (1 cell/thread) ----
        {
            const int wmh   = eb >> 5;
            const int mt    = (eb >> 4) & 1;
            const int lane_ = (eb & 7) * 4 + (ej >> 1);
            const int v     = ((eb >> 3) & 1) * 2 + (ej & 1);
            float gv[4];
#pragma unroll
            for (int g = 0; g < 4; ++g) {
                const int i = (mt * 4 + g) * 4 + v;
                float s = 0.0f;
#pragma unroll
                for (int k = 0; k < 8; ++k)
                    s += red[(size_t)((wmh * 8 + k) * 32 + lane_) * RED_STRIDE + i];
                gv[g] = s + xg[g];
            }
            float iv = sigmoidf_(gv[0]);
            float fv = sigmoidf_(gv[1]);
            float gg = tanhf_(gv[2]);
            float ov = sigmoidf_(gv[3]);
            float cn = fv * c_reg + iv * gg;
            c_reg = cn;
            float hn = ov * tanhf_(cn);
            out[((size_t)t * BB + eb) * HH + j0 + ej] = hn;
            g_hf[(t + 1) & 1][scat] = f2tf32(hn);   // fragment scatter for t+1
        }
        __syncthreads();   // red reads done before next step reuses it

        // ---- publish ----
        __threadfence();
        if (tid == 0) *(volatile unsigned*)&g_slot[bid] = (unsigned)(t + 1);

        // ---- prefetch x_gates for t+1 ----
        if (t + 1 < TT) {
            const float* p = g_xg + ((size_t)(t + 1) * BB + eb) * G4 + j0 + ej;
#pragma unroll
            for (int g = 0; g < 4; ++g) xg[g] = p[g * HH];
        }
    }
}

// ---------------------------------------------------------------------------
// Launch
// ---------------------------------------------------------------------------
extern "C" void kernel_launch(void* const* d_in, const int* in_sizes, int n_in,
                              void* d_out, int out_size) {
    const float* inputs = (const float*)d_in[0];
    const float* h0     = (const float*)d_in[1];
    const float* c0     = (const float*)d_in[2];
    const float* W_ih   = (const float*)d_in[3];
    const float* W_hh   = (const float*)d_in[4];
    const float* b_ih   = (const float*)d_in[5];
    const float* b_hh   = (const float*)d_in[6];
    float* out = (float*)d_out;

    cudaFuncSetAttribute(lstm_persistent,
                         cudaFuncAttributeMaxDynamicSharedMemorySize,
                         SMEM_WORDS * 4);

    prep_kernel<<<BB, 256>>>(h0);
    xgates_kernel<<<dim3(63, 512), 256>>>(inputs, W_ih, b_ih, b_hh);
    lstm_persistent<<<NBLK, 512, SMEM_WORDS * 4>>>(c0, W_hh, out);
}

// round 13
// speedup vs baseline: 3.1800x; 1.1797x over previous
#include <cuda_runtime.h>
#include <cuda_fp16.h>
#include <cstdint>
#include <math.h>

// Problem constants
#define TT 512
#define BB 64
#define II 300
#define HH 1000
#define G4 4000
#define KP 1024           // padded K
#define NBLK 125          // persistent blocks (<=148 SMs -> co-resident)

// ---------------------------------------------------------------------------
// Device scratch (allocation-free: __device__ globals)
// ---------------------------------------------------------------------------
__device__ float g_xg[(size_t)TT * BB * G4];   // x_gates [T,B,4H]
__device__ __half g_hf[2][BB * KP];            // h as fp16 MMA fragments, 2 parities
__device__ unsigned g_slot[128];               // per-block step slots

// ---------------------------------------------------------------------------
// helpers
// ---------------------------------------------------------------------------
__device__ __forceinline__ unsigned f2tf32(float x) {
    unsigned y;
    asm("cvt.rna.tf32.f32 %0, %1;" : "=r"(y) : "f"(x));
    return y;
}
__device__ __forceinline__ void mma_tf32(float c[4], unsigned a0, unsigned a1,
                                         unsigned a2, unsigned a3,
                                         unsigned b0, unsigned b1) {
    asm volatile(
        "mma.sync.aligned.m16n8k8.row.col.f32.tf32.tf32.f32 "
        "{%0,%1,%2,%3}, {%4,%5,%6,%7}, {%8,%9}, {%0,%1,%2,%3};"
        : "+f"(c[0]), "+f"(c[1]), "+f"(c[2]), "+f"(c[3])
        : "r"(a0), "r"(a1), "r"(a2), "r"(a3), "r"(b0), "r"(b1));
}
__device__ __forceinline__ void mma_f16(float c[4], unsigned a0, unsigned a1,
                                        unsigned a2, unsigned a3,
                                        unsigned b0, unsigned b1) {
    asm volatile(
        "mma.sync.aligned.m16n8k16.row.col.f32.f16.f16.f32 "
        "{%0,%1,%2,%3}, {%4,%5,%6,%7}, {%8,%9}, {%0,%1,%2,%3};"
        : "+f"(c[0]), "+f"(c[1]), "+f"(c[2]), "+f"(c[3])
        : "r"(a0), "r"(a1), "r"(a2), "r"(a3), "r"(b0), "r"(b1));
}
__device__ __forceinline__ float sigmoidf_(float x) { return 1.0f / (1.0f + __expf(-x)); }
__device__ __forceinline__ float tanhf_(float x) { return 2.0f / (1.0f + __expf(-2.0f * x)) - 1.0f; }

// fp16 fragment half-index of A element (b, kglob) for m16n8k16.row:
//   a0:(g,2t/2t+1) a1:(g+8,..) a2:(g,2t+8/9) a3:(g+8,..), lane = g*4 + t
__device__ __forceinline__ int frag_half_of(int b, int kglob) {
    int wm = b >> 5, mt = (b >> 4) & 1, r = b & 15, g = r & 7, rsel = r >> 3;
    int ch = kglob >> 7, kr = kglob & 127;
    int wk = kr >> 4, kl = kr & 15;
    int p = kl >> 1, lo = kl & 1, tq = p & 3, ksel = p >> 2;
    int lane = g * 4 + tq;
    int reg  = ksel * 2 + rsel;
    int word = ((((wm * 8 + wk) * 8 + ch) * 2 + mt) * 32 + lane) * 4 + reg;
    return word * 2 + lo;
}

// ---------------------------------------------------------------------------
// Kernel 1: x_gates GEMM (tf32, unchanged numerics)  +  prep row (y==512):
//           h0 -> g_hf[0] fp16 fragments, slot reset.
// ---------------------------------------------------------------------------
__global__ void __launch_bounds__(256) xgates_kernel(
    const float* __restrict__ X, const float* __restrict__ Wih,
    const float* __restrict__ b_ih, const float* __restrict__ b_hh,
    const float* __restrict__ h0)
{
    if (blockIdx.y == 512) {               // prep row: 63 blocks
        const int bx = blockIdx.x;
        if (bx == 0 && threadIdx.x < 128) g_slot[threadIdx.x] = 0u;
        for (int b = bx; b < BB; b += 63) {
            for (int k = threadIdx.x; k < HH; k += 256)
                g_hf[0][frag_half_of(b, k)] = __float2half_rn(h0[b * HH + k]);
        }
        return;
    }

    const int m0 = blockIdx.y * 64;
    const int n0 = blockIdx.x * 64;
    const int tid  = threadIdx.x;
    const int lane = tid & 31;
    const int warp = tid >> 5;
    const int wm = warp & 3;
    const int wn = warp >> 2;

    __shared__ unsigned a_s[64][17];
    __shared__ unsigned b_s[64][17];

    float acc[4][4];
#pragma unroll
    for (int s = 0; s < 4; ++s)
#pragma unroll
        for (int i = 0; i < 4; ++i) acc[s][i] = 0.0f;

    const int g_id = lane >> 2;
    const int t_id = lane & 3;

    for (int ch = 0; ch < 19; ++ch) {
        const int k0 = ch * 16;
#pragma unroll
        for (int it = 0; it < 4; ++it) {
            int i = tid + it * 256;
            int m = i >> 4, k = i & 15;
            float va = (k0 + k < II) ? X[(size_t)(m0 + m) * II + k0 + k] : 0.0f;
            a_s[m][k] = f2tf32(va);
            int r = n0 + m;
            float vb = (r < G4 && k0 + k < II) ? Wih[(size_t)r * II + k0 + k] : 0.0f;
            b_s[m][k] = f2tf32(vb);
        }
        __syncthreads();

#pragma unroll
        for (int kk = 0; kk < 2; ++kk) {
            const int kb = kk * 8;
            unsigned a[4];
            a[0] = a_s[wm * 16 + g_id][kb + t_id];
            a[1] = a_s[wm * 16 + g_id + 8][kb + t_id];
            a[2] = a_s[wm * 16 + g_id][kb + t_id + 4];
            a[3] = a_s[wm * 16 + g_id + 8][kb + t_id + 4];
#pragma unroll
            for (int s = 0; s < 4; ++s) {
                unsigned b0 = b_s[wn * 32 + s * 8 + g_id][kb + t_id];
                unsigned b1 = b_s[wn * 32 + s * 8 + g_id][kb + t_id + 4];
                mma_tf32(acc[s], a[0], a[1], a[2], a[3], b0, b1);
            }
        }
        __syncthreads();
    }

#pragma unroll
    for (int s = 0; s < 4; ++s) {
        int n = n0 + wn * 32 + s * 8 + 2 * t_id;
        int row = m0 + wm * 16 + g_id;
        if (n < G4) {
            float bia0 = b_ih[n] + b_hh[n];
            float bia1 = b_ih[n + 1] + b_hh[n + 1];
            g_xg[(size_t)row * G4 + n]           = acc[s][0] + bia0;
            g_xg[(size_t)row * G4 + n + 1]       = acc[s][1] + bia1;
            g_xg[(size_t)(row + 8) * G4 + n]     = acc[s][2] + bia0;
            g_xg[(size_t)(row + 8) * G4 + n + 1] = acc[s][3] + bia1;
        }
    }
}

// ---------------------------------------------------------------------------
// Kernel 2: persistent LSTM, 125 blocks x 512 threads, fp16 m16n8k16 MMA.
//   A (h) read directly from fragment-ordered g_hf[t&1] via LDG.128 (1 uint4
//   per chunk x mt). B = W_hh slice resident in smem as packed half2 (32
//   gate-major rows x 512 half2, K-padded). Warp (wk=warp&7, wm=warp>>3):
//   m32 x n32 x k16-per-chunk; 8-way K reduction; fused cell update; h_t
//   scattered as fp16 into g_hf[(t+1)&1]; slot barrier.
// ---------------------------------------------------------------------------
#define WS_STRIDE 516               // half2 words; 516 % 32 == 4 -> conflict-free
#define W_WORDS (32 * WS_STRIDE)    // 16512 words
#define RED_STRIDE 33
#define SMEM_WORDS (W_WORDS + 512 * RED_STRIDE)

__global__ void __launch_bounds__(512, 1) lstm_persistent(
    const float* __restrict__ c0, const float* __restrict__ Whh,
    float* __restrict__ out)
{
    extern __shared__ unsigned sm[];
    unsigned* W_s = sm;                         // [32][516] packed half2
    float*    red = (float*)(sm + W_WORDS);     // [512][33]

    const int bid  = blockIdx.x;
    const int j0   = bid * 8;
    const int tid  = threadIdx.x;
    const int lane = tid & 31;
    const int warp = tid >> 5;
    const int wk = warp & 7;        // k16 slice within each k128 chunk
    const int wm = warp >> 3;       // m-half (32 batch rows)
    const int g_id = lane >> 2;
    const int t_id = lane & 3;

    // ---- resident W: 32 gate-major rows x 512 half2 (zero-padded) ----
    for (int idx = tid; idx < 32 * 512; idx += 512) {
        int n = idx >> 9, k2 = idx & 511;
        int row = (n >> 3) * HH + j0 + (n & 7);
        int k = k2 * 2;
        float v0 = (k < HH)     ? Whh[(size_t)row * HH + k]     : 0.0f;
        float v1 = (k + 1 < HH) ? Whh[(size_t)row * HH + k + 1] : 0.0f;
        __half2 hv = __floats2half2_rn(v0, v1);
        W_s[n * WS_STRIDE + k2] = *(unsigned*)&hv;
    }

    // ---- per-thread cell state + xg prefetch (1 cell: b=tid>>3, jj=tid&7) ----
    const int eb = tid >> 3, ej = tid & 7;
    float c_reg = c0[eb * HH + j0 + ej];
    float xg[4];
    {
        const float* p = g_xg + (size_t)eb * G4 + j0 + ej;
#pragma unroll
        for (int g = 0; g < 4; ++g) xg[g] = p[g * HH];
    }
    const int scat = frag_half_of(eb, j0 + ej);   // epilogue scatter (half index)
    __syncthreads();

    // per-warp fragment base: uint4 index = (((wm*8+wk)*8+ch)*2+mt)*32 + lane
    const int fvec = ((wm * 8 + wk) * 8) * 2 * 32 + lane;

    for (int t = 0; t < TT; ++t) {
        // ---- slot barrier: wait for all blocks to publish h_{t-1} ----
        if (t > 0) {
            if (warp == 0) {
                const unsigned tgt = (unsigned)t;
                for (;;) {
                    bool ok = true;
#pragma unroll
                    for (int s = 0; s < 4; ++s) {
                        int id = lane + 32 * s;
                        if (id < NBLK) ok &= (*(volatile unsigned*)&g_slot[id] >= tgt);
                    }
                    if (__ballot_sync(0xffffffffu, ok) == 0xffffffffu) break;
                }
                __threadfence();
            }
            __syncthreads();
        }
        const uint4* Af = (const uint4*)g_hf[t & 1];

        float acc[2][4][4];
#pragma unroll
        for (int mt = 0; mt < 2; ++mt)
#pragma unroll
            for (int nt = 0; nt < 4; ++nt)
#pragma unroll
                for (int i = 0; i < 4; ++i) acc[mt][nt][i] = 0.0f;

        // ---- K loop: 8 chunks; A via direct LDG.128, double-buffered ----
        uint4 av[2][2];   // [buf][mt]
        av[0][0] = Af[fvec];
        av[0][1] = Af[fvec + 32];
#pragma unroll
        for (int ch = 0; ch < 8; ++ch) {
            if (ch < 7) {
                av[(ch + 1) & 1][0] = Af[fvec + (ch + 1) * 64];
                av[(ch + 1) & 1][1] = Af[fvec + (ch + 1) * 64 + 32];
            }
            const uint4* a = av[ch & 1];
            const int kg2 = ch * 64 + wk * 8;   // half2-word offset in W_s row
#pragma unroll
            for (int nt = 0; nt < 4; ++nt) {
                unsigned b0 = W_s[(nt * 8 + g_id) * WS_STRIDE + kg2 + t_id];
                unsigned b1 = W_s[(nt * 8 + g_id) * WS_STRIDE + kg2 + t_id + 4];
                mma_f16(acc[0][nt], a[0].x, a[0].y, a[0].z, a[0].w, b0, b1);
                mma_f16(acc[1][nt], a[1].x, a[1].y, a[1].z, a[1].w, b0, b1);
            }
        }

        // ---- dump partials ----
        {
            float* my = red + (size_t)tid * RED_STRIDE;
#pragma unroll
            for (int mt = 0; mt < 2; ++mt)
#pragma unroll
                for (int nt = 0; nt < 4; ++nt)
#pragma unroll
                    for (int v = 0; v < 4; ++v)
                        my[(mt * 4 + nt) * 4 + v] = acc[mt][nt][v];
        }
        __syncthreads();

        // ---- 8-way K reduction + fused cell update (1 cell/thread) ----
        {
            const int wmh   = eb >> 5;
            const int mt    = (eb >> 4) & 1;
            const int lane_ = (eb & 7) * 4 + (ej >> 1);
            const int v     = ((eb >> 3) & 1) * 2 + (ej & 1);
            float gv[4];
#pragma unroll
            for (int g = 0; g < 4; ++g) {
                const int i = (mt * 4 + g) * 4 + v;
                float s = 0.0f;
#pragma unroll
                for (int k = 0; k < 8; ++k)
                    s += red[(size_t)((wmh * 8 + k) * 32 + lane_) * RED_STRIDE + i];
                gv[g] = s + xg[g];
            }
            float iv = sigmoidf_(gv[0]);
            float fv = sigmoidf_(gv[1]);
            float gg = tanhf_(gv[2]);
            float ov = sigmoidf_(gv[3]);
            float cn = fv * c_reg + iv * gg;
            c_reg = cn;
            float hn = ov * tanhf_(cn);
            out[((size_t)t * BB + eb) * HH + j0 + ej] = hn;
            g_hf[(t + 1) & 1][scat] = __float2half_rn(hn);
        }
        __syncthreads();   // red reads done before next step reuses it

        // ---- publish ----
        __threadfence();
        if (tid == 0) *(volatile unsigned*)&g_slot[bid] = (unsigned)(t + 1);

        // ---- prefetch x_gates for t+1 ----
        if (t + 1 < TT) {
            const float* p = g_xg + ((size_t)(t + 1) * BB + eb) * G4 + j0 + ej;
#pragma unroll
            for (int g = 0; g < 4; ++g) xg[g] = p[g * HH];
        }
    }
}

// ---------------------------------------------------------------------------
// Launch
// ---------------------------------------------------------------------------
extern "C" void kernel_launch(void* const* d_in, const int* in_sizes, int n_in,
                              void* d_out, int out_size) {
    const float* inputs = (const float*)d_in[0];
    const float* h0     = (const float*)d_in[1];
    const float* c0     = (const float*)d_in[2];
    const float* W_ih   = (const float*)d_in[3];
    const float* W_hh   = (const float*)d_in[4];
    const float* b_ih   = (const float*)d_in[5];
    const float* b_hh   = (const float*)d_in[6];
    float* out = (float*)d_out;

    cudaFuncSetAttribute(lstm_persistent,
                         cudaFuncAttributeMaxDynamicSharedMemorySize,
                         SMEM_WORDS * 4);

    xgates_kernel<<<dim3(63, 513), 256>>>(inputs, W_ih, b_ih, b_hh, h0);
    lstm_persistent<<<NBLK, 512, SMEM_WORDS * 4>>>(c0, W_hh, out);
}